// round 8
// baseline (speedup 1.0000x reference)
#include <cuda_runtime.h>
#include <cuda_fp16.h>
#include <cuda_bf16.h>
#include <cstdint>

// GeoEncoder v7: v6 + matvec restructured c4-outer/h-inner so projection
// weights are read from smem once per warp-iter (24 LDS) instead of once
// per point (96 LDS) -> smem crossbar load cut ~45%.

#define RES   512
#define RANK  48
#define PADC  64
#define OUT_C 32

typedef unsigned long long u64;

__device__ __half g_planes_h[3ull * RES * RES * PADC];  // ~100 MB
__device__ __half g_lines_h[3 * RES * PADC];            // 192 KB

// ---- packed f32x2 helpers -------------------------------------------------
__device__ __forceinline__ u64 pk2(float lo, float hi) {
    u64 r; asm("mov.b64 %0,{%1,%2};" : "=l"(r) : "f"(lo), "f"(hi)); return r;
}
__device__ __forceinline__ float2 upk2(u64 a) {
    float2 f; asm("mov.b64 {%0,%1},%2;" : "=f"(f.x), "=f"(f.y) : "l"(a)); return f;
}
__device__ __forceinline__ u64 f2fma(u64 a, u64 b, u64 c) {
    u64 d; asm("fma.rn.f32x2 %0,%1,%2,%3;" : "=l"(d) : "l"(a), "l"(b), "l"(c)); return d;
}
__device__ __forceinline__ u64 f2mul(u64 a, u64 b) {
    u64 d; asm("mul.rn.f32x2 %0,%1,%2;" : "=l"(d) : "l"(a), "l"(b)); return d;
}
__device__ __forceinline__ u64 h2f2(unsigned h) {
    float2 f = __half22float2(*reinterpret_cast<const __half2*>(&h));
    return pk2(f.x, f.y);
}
__device__ __forceinline__ u64 mkpair(unsigned lo, unsigned hi) {
    u64 r; asm("mov.b64 %0,{%1,%2};" : "=l"(r) : "r"(lo), "r"(hi)); return r;
}

// ---------------------------------------------------------------------------
// Prep: planes [R][512][512] f32 -> [p][y][x][64] fp16 (pad 0);
//       lines  [R][512]       -> [l][z][64] fp16 (pad 0).  z==3 does lines.
// ---------------------------------------------------------------------------
__global__ void prep_grids(const float* __restrict__ pxy,
                           const float* __restrict__ pxz,
                           const float* __restrict__ pyz,
                           const float* __restrict__ lz,
                           const float* __restrict__ ly,
                           const float* __restrict__ lx) {
    if (blockIdx.z == 3) {
        const int total = 3 * RES * PADC;
        int i = ((blockIdx.y * gridDim.x + blockIdx.x) * blockDim.x) + threadIdx.x;
        if (i < total) {
            int p   = i / (RES * PADC);
            int rem = i - p * (RES * PADC);
            int z   = rem / PADC;
            int r   = rem - z * PADC;
            const float* in = (p == 0) ? lz : (p == 1) ? ly : lx;
            g_lines_h[i] = (r < RANK) ? __float2half(in[r * RES + z]) : __half(0.0f);
        }
        return;
    }
    __shared__ float s[128 * 49];
    const int p  = blockIdx.z;
    const int y  = blockIdx.y;
    const int xb = blockIdx.x * 128;
    const float* in = (p == 0) ? pxy : (p == 1) ? pxz : pyz;

    for (int i = threadIdx.x; i < RANK * 128; i += blockDim.x) {
        int r  = i >> 7;
        int xl = i & 127;
        s[xl * 49 + r] = in[(size_t)r * (RES * RES) + (size_t)y * RES + xb + xl];
    }
    __syncthreads();

    __half2* outp = reinterpret_cast<__half2*>(
        g_planes_h + ((size_t)p * (RES * RES) + (size_t)y * RES + xb) * PADC);
    for (int i = threadIdx.x; i < 128 * (PADC / 2); i += blockDim.x) {
        int xl = i >> 5;
        int c  = (i & 31) * 2;
        float a = (c     < RANK) ? s[xl * 49 + c]     : 0.0f;
        float b = (c + 1 < RANK) ? s[xl * 49 + c + 1] : 0.0f;
        outp[i] = __floats2half2_rn(a, b);
    }
}

// ---------------------------------------------------------------------------
// Main kernel. Warp = 4 points; 8 lanes/point, each carries 8 channels.
// Matvec c4-outer: each weight pair loaded once, 4 point-accumulators.
// ---------------------------------------------------------------------------
__global__ void __launch_bounds__(256, 4)
geo_main(const float* __restrict__ coords,
         const float* __restrict__ projw,
         const float* __restrict__ projb,
         float* __restrict__ out, int npts) {
    __shared__ alignas(16) u64 s_vm[8][4][32];   // 32 pairs/point: t=6,7 pad area
    __shared__ u64 s_w[24][OUT_C];               // transposed packed weights

    const int tid  = threadIdx.x;
    const int warp = tid >> 5;
    const int lane = tid & 31;
    const int sp   = lane >> 3;
    const int t    = lane & 7;
    const int o    = lane;                        // output channel for matvec

    // Stage weights once per block (transposed, lane-contiguous).
    for (int i = tid; i < 24 * OUT_C; i += blockDim.x) {
        int c2 = i >> 5, oo = i & 31;
        s_w[c2][oo] = pk2(projw[oo * RANK + 2 * c2], projw[oo * RANK + 2 * c2 + 1]);
    }
    __syncthreads();
    const float bo = projb[o];

    const int warp_global = blockIdx.x * (blockDim.x >> 5) + warp;
    const int warp_count  = gridDim.x * (blockDim.x >> 5);
    const int maxcidx     = npts * 3 - 1;

    for (int pb = warp_global * 4; pb < npts; pb += warp_count * 4) {
        // Coalesced coord fetch: 12 lanes load, everyone shuffles.
        float cv = 0.0f;
        if (lane < 12) cv = __ldcs(coords + min(3 * pb + lane, maxcidx));
        const float cx = __shfl_sync(0xffffffffu, cv, sp * 3 + 0) * 2.0f - 1.0f;
        const float cy = __shfl_sync(0xffffffffu, cv, sp * 3 + 1) * 2.0f - 1.0f;
        const float cz = __shfl_sync(0xffffffffu, cv, sp * 3 + 2) * 2.0f - 1.0f;

        u64 acc[4];
        #pragma unroll
        for (int k = 0; k < 4; k++) acc[k] = pk2(0.0f, 0.0f);

        #pragma unroll
        for (int q = 0; q < 3; q++) {
            const float gx = (q == 2) ? cy : cx;
            const float gy = (q == 0) ? cy : cz;
            const float gl = (q == 0) ? cz : ((q == 1) ? cy : cx);

            float px = fminf(fmaxf((gx + 1.0f) * 0.5f * 511.0f, 0.0f), 511.0f);
            float py = fminf(fmaxf((gy + 1.0f) * 0.5f * 511.0f, 0.0f), 511.0f);
            float pz = fminf(fmaxf((gl + 1.0f) * 0.5f * 511.0f, 0.0f), 511.0f);
            const int x0 = (int)floorf(px), y0 = (int)floorf(py), z0 = (int)floorf(pz);
            const int x1 = min(x0 + 1, 511), y1 = min(y0 + 1, 511), z1 = min(z0 + 1, 511);
            const float wx = px - (float)x0;
            const float wy = py - (float)y0;
            const float wz = pz - (float)z0;

            const float w00 = (1.0f - wy) * (1.0f - wx);
            const float w01 = (1.0f - wy) * wx;
            const float w10 = wy * (1.0f - wx);
            const float w11 = wy * wx;
            const u64 w00p = pk2(w00, w00), w01p = pk2(w01, w01);
            const u64 w10p = pk2(w10, w10), w11p = pk2(w11, w11);
            const u64 lz0p = pk2(1.0f - wz, 1.0f - wz), wzp = pk2(wz, wz);

            const __half* gp = g_planes_h + (size_t)q * (RES * RES * PADC);
            const uint4 u00 = __ldg(reinterpret_cast<const uint4*>(gp + ((size_t)(y0 * RES) + x0) * PADC) + t);
            const uint4 u01 = __ldg(reinterpret_cast<const uint4*>(gp + ((size_t)(y0 * RES) + x1) * PADC) + t);
            const uint4 u10 = __ldg(reinterpret_cast<const uint4*>(gp + ((size_t)(y1 * RES) + x0) * PADC) + t);
            const uint4 u11 = __ldg(reinterpret_cast<const uint4*>(gp + ((size_t)(y1 * RES) + x1) * PADC) + t);
            const uint4 a0  = __ldg(reinterpret_cast<const uint4*>(g_lines_h + (q * RES + z0) * PADC) + t);
            const uint4 a1  = __ldg(reinterpret_cast<const uint4*>(g_lines_h + (q * RES + z1) * PADC) + t);

            #pragma unroll
            for (int k = 0; k < 4; k++) {
                const u64 f00 = h2f2((&u00.x)[k]);
                const u64 f01 = h2f2((&u01.x)[k]);
                const u64 f10 = h2f2((&u10.x)[k]);
                const u64 f11 = h2f2((&u11.x)[k]);
                const u64 g0  = h2f2((&a0.x)[k]);
                const u64 g1  = h2f2((&a1.x)[k]);

                const u64 pv = f2fma(f00, w00p,
                                f2fma(f01, w01p,
                                 f2fma(f10, w10p, f2mul(f11, w11p))));
                const u64 lv = f2fma(g0, lz0p, f2mul(g1, wzp));
                acc[k] = f2fma(pv, lv, acc[k]);
            }
        }

        // Stage vm via two STS.128 per lane (t=6,7 write zero pad, in-bounds).
        {
            const float2 a0 = upk2(acc[0]), a1 = upk2(acc[1]);
            const float2 a2 = upk2(acc[2]), a3 = upk2(acc[3]);
            float4* dst = reinterpret_cast<float4*>(&s_vm[warp][sp][t * 4]);
            dst[0] = make_float4(a0.x, a0.y, a1.x, a1.y);
            dst[1] = make_float4(a2.x, a2.y, a3.x, a3.y);
        }
        __syncwarp();

        // Matvec, c4-outer: each weight pair read ONCE, 4 point-accumulators.
        {
            u64 s2[4];
            #pragma unroll
            for (int h = 0; h < 4; h++) s2[h] = pk2(0.0f, 0.0f);

            #pragma unroll
            for (int c4 = 0; c4 < 12; c4++) {
                const u64 w0 = s_w[2 * c4 + 0][o];
                const u64 w1 = s_w[2 * c4 + 1][o];
                #pragma unroll
                for (int h = 0; h < 4; h++) {
                    const uint4 v = reinterpret_cast<const uint4*>(s_vm[warp][h])[c4];
                    s2[h] = f2fma(mkpair(v.x, v.y), w0, s2[h]);
                    s2[h] = f2fma(mkpair(v.z, v.w), w1, s2[h]);
                }
            }

            #pragma unroll
            for (int h = 0; h < 4; h++) {
                const int pp = pb + h;           // uniform across warp
                if (pp < npts) {
                    const float2 f = upk2(s2[h]);
                    __stcs(out + (size_t)pp * OUT_C + o, f.x + f.y + bo);
                }
            }
        }
        __syncwarp();
    }
}

// ---------------------------------------------------------------------------
extern "C" void kernel_launch(void* const* d_in, const int* in_sizes, int n_in,
                              void* d_out, int out_size) {
    const float* coords = (const float*)d_in[0];
    const float* pxy    = (const float*)d_in[1];
    const float* pxz    = (const float*)d_in[2];
    const float* pyz    = (const float*)d_in[3];
    const float* lz     = (const float*)d_in[4];
    const float* ly     = (const float*)d_in[5];
    const float* lx     = (const float*)d_in[6];
    const float* pw     = (const float*)d_in[7];
    const float* pbias  = (const float*)d_in[8];
    float* outp = (float*)d_out;
    const int npts = in_sizes[0] / 3;

    dim3 tgrid(4, RES, 4);
    prep_grids<<<tgrid, 256>>>(pxy, pxz, pyz, lz, ly, lx);
    geo_main<<<592, 256>>>(coords, pw, pbias, outp, npts);
}